// round 15
// baseline (speedup 1.0000x reference)
#include <cuda_runtime.h>
#include <cuda_bf16.h>

// GNNIntraAgg: out[b, :] = relu( (1/K) * sum_k features[neigh_ids[b,k], :] )
// B=16384, K=32, N=100000, D=256 (fp32).
//
// FINAL (= R10, best measured: 35.3us). At the LTS (L2->SM) service
// ceiling: 536 MB compulsory random-gather traffic at ~15.2 TB/s effective
// (~6300 B/cyc path-independent chip cap).
//
// Design (each element justified by a measured A/B):
//  - warp-per-output-row, 4-warp CTAs (block sweep 8/4/2: 4 is optimal)
//  - warp-private smem id staging + __syncwarp only (block barrier cost -1.2us)
//  - LDG.256 (ld.global.nc.L2::evict_last.v8.b32): 256-bit gathers, table
//    kept L2-resident; manual 4-deep batches = 128 B in flight per thread
//    (depth sweep 64/128/256 B: concave, peak at 128 B; unbatched loop
//    serializes in ptxas and loses 8us)
//  - natural register allocation (44 regs, 5-11 CTAs/SM); every
//    __launch_bounds__ cap degraded the load schedule
//  - streaming output stores (__stcs) so the 16 MB output doesn't evict
//    the 102 MB feature table from L2.

#define K_NEIGH 32
#define WARPS_PER_BLOCK 4
#define THREADS (WARPS_PER_BLOCK * 32)   // 128
#define LBATCH 4                          // outstanding LDG.256 per thread

__device__ __forceinline__ void ldg256_evict_last(const float* p, float4& a, float4& b)
{
    asm volatile("ld.global.nc.L2::evict_last.v8.b32 "
                 "{%0,%1,%2,%3,%4,%5,%6,%7}, [%8];"
                 : "=f"(a.x), "=f"(a.y), "=f"(a.z), "=f"(a.w),
                   "=f"(b.x), "=f"(b.y), "=f"(b.z), "=f"(b.w)
                 : "l"(p));
}

__global__ __launch_bounds__(THREADS)
void gnn_agg_kernel(const int* __restrict__ neigh_ids,
                    const float* __restrict__ feat,
                    float4* __restrict__ out,
                    int B)
{
    __shared__ int s_ids[WARPS_PER_BLOCK][K_NEIGH];

    const int tid  = threadIdx.x;
    const int row0 = blockIdx.x * WARPS_PER_BLOCK;

    const int w    = tid >> 5;        // warp = output row within block
    const int lane = tid & 31;        // lane = 32B chunk of the feature row

    // Warp-local id staging: warp w's lanes write s_ids[w][*] only.
    s_ids[w][lane] = neigh_ids[(row0 + w) * K_NEIGH + lane];
    __syncwarp();                     // intra-warp visibility; no block barrier

    float acc[8];
#pragma unroll
    for (int i = 0; i < 8; ++i) acc[i] = 0.f;

#pragma unroll
    for (int kb = 0; kb < K_NEIGH; kb += LBATCH) {
        float4 va[LBATCH], vb[LBATCH];
        // Front-batch 4 independent 32B gathers -> 128 B in flight per thread.
#pragma unroll
        for (int j = 0; j < LBATCH; ++j) {
            const int id = s_ids[w][kb + j];             // warp-broadcast read
            const float* p = feat + (long)id * 256 + lane * 8;
            ldg256_evict_last(p, va[j], vb[j]);
        }
#pragma unroll
        for (int j = 0; j < LBATCH; ++j) {
            acc[0] += va[j].x;  acc[1] += va[j].y;
            acc[2] += va[j].z;  acc[3] += va[j].w;
            acc[4] += vb[j].x;  acc[5] += vb[j].y;
            acc[6] += vb[j].z;  acc[7] += vb[j].w;
        }
    }

    const float inv = 1.0f / (float)K_NEIGH;
    float4 o0, o1;
    o0.x = fmaxf(acc[0] * inv, 0.f);  o0.y = fmaxf(acc[1] * inv, 0.f);
    o0.z = fmaxf(acc[2] * inv, 0.f);  o0.w = fmaxf(acc[3] * inv, 0.f);
    o1.x = fmaxf(acc[4] * inv, 0.f);  o1.y = fmaxf(acc[5] * inv, 0.f);
    o1.z = fmaxf(acc[6] * inv, 0.f);  o1.w = fmaxf(acc[7] * inv, 0.f);

    // Streaming stores: don't evict the feature table from L2.
    float4* orow = out + (long)(row0 + w) * 64 + lane * 2;
    __stcs(orow,     o0);
    __stcs(orow + 1, o1);
}

extern "C" void kernel_launch(void* const* d_in, const int* in_sizes, int n_in,
                              void* d_out, int out_size)
{
    const int* neigh_ids = (const int*)d_in[0];     // [B, K] int32
    const float* feat    = (const float*)d_in[1];   // [N, D] fp32
    float4* out          = (float4*)d_out;          // [B, D] fp32

    const int B = in_sizes[0] / K_NEIGH;            // 16384
    const int grid = B / WARPS_PER_BLOCK;           // 4096

    gnn_agg_kernel<<<grid, THREADS>>>(neigh_ids, feat, out, B);
}

// round 17
// speedup vs baseline: 1.0507x; 1.0507x over previous
#include <cuda_runtime.h>
#include <cuda_bf16.h>

// GNNIntraAgg: out[b, :] = relu( (1/K) * sum_k features[neigh_ids[b,k], :] )
// B=16384, K=32, N=100000, D=256 (fp32).
//
// FINAL (R10 configuration; best measured 35.3us, run-to-run noise ±2us).
// At the LTS (L2->SM) service ceiling for random gathers: 536 MB compulsory
// traffic at ~15 TB/s effective (~6300 B/cyc path-independent chip cap).
//
// Design, each element justified by a measured A/B:
//  - warp-per-output-row, 4-warp CTAs (block sweep 8/4/2 warps: all within
//    noise; 4 measured best)
//  - warp-private smem id staging + __syncwarp only (removing the block
//    barrier was a reproducible -1.2us)
//  - LDG.256 gathers (ld.global.nc.L2::evict_last.v8.b32): table kept
//    L2-resident; manual 4-deep batches = 128 B in flight per thread
//    (depth sweep 64/128/256 B concave with peak at 128 B; letting ptxas
//    schedule an unbatched loop serializes the loads and costs +8us)
//  - natural register allocation (44 regs): every __launch_bounds__ cap
//    tried (40, 80) broke the 4-deep load batching and regressed
//  - streaming output stores (__stcs) so the 16 MB output doesn't evict
//    the 102 MB feature table from L2.
//
// Rejected by measurement: shfl-broadcast ids (+4.7us), persistent grid +
// id prefetch (+0.6us), deeper MLP at lower occupancy (+9us), higher
// occupancy at lower MLP (+9-13us), unbatched full unroll (+8us).

#define K_NEIGH 32
#define WARPS_PER_BLOCK 4
#define THREADS (WARPS_PER_BLOCK * 32)   // 128
#define LBATCH 4                          // outstanding LDG.256 per thread

__device__ __forceinline__ void ldg256_evict_last(const float* p, float4& a, float4& b)
{
    asm volatile("ld.global.nc.L2::evict_last.v8.b32 "
                 "{%0,%1,%2,%3,%4,%5,%6,%7}, [%8];"
                 : "=f"(a.x), "=f"(a.y), "=f"(a.z), "=f"(a.w),
                   "=f"(b.x), "=f"(b.y), "=f"(b.z), "=f"(b.w)
                 : "l"(p));
}

__global__ __launch_bounds__(THREADS)
void gnn_agg_kernel(const int* __restrict__ neigh_ids,
                    const float* __restrict__ feat,
                    float4* __restrict__ out,
                    int B)
{
    __shared__ int s_ids[WARPS_PER_BLOCK][K_NEIGH];

    const int tid  = threadIdx.x;
    const int row0 = blockIdx.x * WARPS_PER_BLOCK;

    const int w    = tid >> 5;        // warp = output row within block
    const int lane = tid & 31;        // lane = 32B chunk of the feature row

    // Warp-local id staging: warp w's lanes write s_ids[w][*] only.
    s_ids[w][lane] = neigh_ids[(row0 + w) * K_NEIGH + lane];
    __syncwarp();                     // intra-warp visibility; no block barrier

    float acc[8];
#pragma unroll
    for (int i = 0; i < 8; ++i) acc[i] = 0.f;

#pragma unroll
    for (int kb = 0; kb < K_NEIGH; kb += LBATCH) {
        float4 va[LBATCH], vb[LBATCH];
        // Front-batch 4 independent 32B gathers -> 128 B in flight per thread.
#pragma unroll
        for (int j = 0; j < LBATCH; ++j) {
            const int id = s_ids[w][kb + j];             // warp-broadcast read
            const float* p = feat + (long)id * 256 + lane * 8;
            ldg256_evict_last(p, va[j], vb[j]);
        }
#pragma unroll
        for (int j = 0; j < LBATCH; ++j) {
            acc[0] += va[j].x;  acc[1] += va[j].y;
            acc[2] += va[j].z;  acc[3] += va[j].w;
            acc[4] += vb[j].x;  acc[5] += vb[j].y;
            acc[6] += vb[j].z;  acc[7] += vb[j].w;
        }
    }

    const float inv = 1.0f / (float)K_NEIGH;
    float4 o0, o1;
    o0.x = fmaxf(acc[0] * inv, 0.f);  o0.y = fmaxf(acc[1] * inv, 0.f);
    o0.z = fmaxf(acc[2] * inv, 0.f);  o0.w = fmaxf(acc[3] * inv, 0.f);
    o1.x = fmaxf(acc[4] * inv, 0.f);  o1.y = fmaxf(acc[5] * inv, 0.f);
    o1.z = fmaxf(acc[6] * inv, 0.f);  o1.w = fmaxf(acc[7] * inv, 0.f);

    // Streaming stores: don't evict the feature table from L2.
    float4* orow = out + (long)(row0 + w) * 64 + lane * 2;
    __stcs(orow,     o0);
    __stcs(orow + 1, o1);
}

extern "C" void kernel_launch(void* const* d_in, const int* in_sizes, int n_in,
                              void* d_out, int out_size)
{
    const int* neigh_ids = (const int*)d_in[0];     // [B, K] int32
    const float* feat    = (const float*)d_in[1];   // [N, D] fp32
    float4* out          = (float4*)d_out;          // [B, D] fp32

    const int B = in_sizes[0] / K_NEIGH;            // 16384
    const int grid = B / WARPS_PER_BLOCK;           // 4096

    gnn_agg_kernel<<<grid, THREADS>>>(neigh_ids, feat, out, B);
}